// round 5
// baseline (speedup 1.0000x reference)
#include <cuda_runtime.h>
#include <math.h>

// Fixed shapes
#define B_   8
#define NQ_  1280
#define D_   256
#define CIN_ 64
#define H_   200
#define W_   200

// K1 roles: [0,128) conv stage A; [128,160) combine+GEMV stage B
#define NBLK_A 128        // (batch 8) x (ci-chunk 16), 4 input channels per chunk
#define NBLK_B 32
#define NBLK_K1 (NBLK_A + NBLK_B)

// K2: 640 blocks x 256 threads x 4 float4 = 655360 float4 = 8*1280*256 floats
#define NBLK_K2 640
#define F4_PER_BLK 1024   // contiguous; 81920 per batch / 1024 = 80 blocks per batch

// Scratch + sync (no allocations allowed)
__device__ float g_part[B_][16][D_][4];  // conv partials per (batch, ci-chunk, co, corner)
__device__ float g_r[B_][D_];            // per-batch residual row
__device__ unsigned int g_flagA;
__device__ unsigned int g_doneB;

__device__ __forceinline__ unsigned int ld_acq(const unsigned int* p) {
    unsigned int v;
    asm volatile("ld.acquire.gpu.global.u32 %0, [%1];" : "=r"(v) : "l"(p) : "memory");
    return v;
}
__device__ __forceinline__ void red_rel_add(unsigned int* p, unsigned int v) {
    asm volatile("red.release.gpu.global.add.u32 [%0], %1;" :: "l"(p), "r"(v) : "memory");
}

// ============================================================================
// K1: per-batch residual row r[b][256]
// ============================================================================
__global__ __launch_bounds__(256) void k_residual(
    const float* __restrict__ navi,
    const float* __restrict__ bev,
    const float* __restrict__ point_score,
    const float* __restrict__ aws_w,
    const float* __restrict__ aws_b,
    const float* __restrict__ conv_w,
    const float* __restrict__ conv_b,
    const float* __restrict__ out_w,
    const float* __restrict__ out_b)
{
    const int blk = blockIdx.x;
    const int tid = threadIdx.x;

    if (blk < NBLK_A) {
        // ===== Stage A: 3x3 conv at the 4 bilinear corner pixels, 4 ci/block =====
        const int b     = blk >> 4;
        const int chunk = blk & 15;

        const float gx = (navi[2*b+1] * (1.0f/32.0f) + 1.0f) * (0.5f * W_) - 0.5f;
        const float gy = (navi[2*b+0] * (1.0f/32.0f) + 1.0f) * (0.5f * H_) - 0.5f;
        const int x0 = (int)floorf(gx);
        const int y0 = (int)floorf(gy);

        __shared__ float patch[4][16];     // 4x4 patch per local input channel
        __shared__ float smem_w[D_ * 40];  // 36 weights per co, padded to 40 f4-elems

        if (tid < 64) {
            const int ci_l = tid >> 4, pos = tid & 15;
            const int iy = y0 - 1 + (pos >> 2);
            const int ix = x0 - 1 + (pos & 3);
            float v = 0.0f;   // zero padding ('SAME')
            if (iy >= 0 && iy < H_ && ix >= 0 && ix < W_)
                v = bev[((b * CIN_ + chunk * 4 + ci_l) * H_ + iy) * W_ + ix];
            patch[ci_l][pos] = v;
        }

        // Coalesced weight staging: 2304 float4; linear f -> run r (=co), elem j
        {
            const float4* __restrict__ src = (const float4*)conv_w;
            float4* __restrict__ dst = (float4*)smem_w;
            #pragma unroll
            for (int i = 0; i < 9; i++) {
                const int f = i * 256 + tid;
                const int r = f / 9;
                const int j = f - r * 9;
                dst[r * 10 + j] = src[r * 144 + chunk * 9 + j];
            }
        }
        __syncthreads();

        float4 wq[9];
        {
            const float4* __restrict__ wsrc = (const float4*)smem_w + tid * 10;
            #pragma unroll
            for (int j = 0; j < 9; j++) wq[j] = wsrc[j];
        }
        const float* w = (const float*)wq;

        float a0 = 0.f, a1 = 0.f, a2 = 0.f, a3 = 0.f;
        #pragma unroll
        for (int cl = 0; cl < 4; cl++) {
            float p[16];
            #pragma unroll
            for (int j = 0; j < 16; j++) p[j] = patch[cl][j];
            const float* wc = w + cl * 9;
            #pragma unroll
            for (int kh = 0; kh < 3; kh++)
                #pragma unroll
                for (int kw = 0; kw < 3; kw++) {
                    const float wvv = wc[kh * 3 + kw];
                    a0 = fmaf(wvv, p[(kh + 0) * 4 + (kw + 0)], a0);
                    a1 = fmaf(wvv, p[(kh + 0) * 4 + (kw + 1)], a1);
                    a2 = fmaf(wvv, p[(kh + 1) * 4 + (kw + 0)], a2);
                    a3 = fmaf(wvv, p[(kh + 1) * 4 + (kw + 1)], a3);
                }
        }
        *(float4*)&g_part[b][chunk][tid][0] = make_float4(a0, a1, a2, a3);
        __syncthreads();
        if (tid == 0) red_rel_add(&g_flagA, 1);   // release: orders partials

    } else {
        // ===== Stage B: bias+ReLU+bilinear+aws, then 256x256 GEMV ================
        const int blkB  = blk - NBLK_A;
        const int b     = blkB >> 2;
        const int rg    = blkB & 3;
        const int row_l = tid >> 2;
        const int qq    = tid & 3;
        const int d     = rg * 64 + row_l;

        // Prefetch out_w quarter-row before spinning
        const float4* __restrict__ wp = (const float4*)(out_w + d * D_ + qq * 64);
        float4 wreg[16];
        #pragma unroll
        for (int j = 0; j < 16; j++) wreg[j] = wp[j];
        const float ob = out_b[d];

        const int c = tid;
        const float v = (c < 128) ? point_score[2*b+1] : point_score[2*b+0];
        const int kk = (c & 127) >> 1;
        const float inv_t = exp2f(-(float)kk * (13.28771237954945f / 64.0f));
        const float arg = v * 6.283185307179586f * inv_t;
        const float e = (c & 1) ? cosf(arg) : sinf(arg);
        const float awsterm = e * aws_w[c];
        const float awsbias = aws_b[0];
        const float cb = conv_b[c];

        const float gx = (navi[2*b+1] * (1.0f/32.0f) + 1.0f) * (0.5f * W_) - 0.5f;
        const float gy = (navi[2*b+0] * (1.0f/32.0f) + 1.0f) * (0.5f * H_) - 0.5f;
        const float x0f = floorf(gx), y0f = floorf(gy);
        const float wx1 = gx - x0f, wy1 = gy - y0f;
        const int x0 = (int)x0f, y0 = (int)y0f;
        float wt0 = (1.f - wx1) * (1.f - wy1);
        float wt1 = wx1 * (1.f - wy1);
        float wt2 = (1.f - wx1) * wy1;
        float wt3 = wx1 * wy1;
        if (!(x0   >= 0 && x0   < W_ && y0   >= 0 && y0   < H_)) wt0 = 0.f;
        if (!(x0+1 >= 0 && x0+1 < W_ && y0   >= 0 && y0   < H_)) wt1 = 0.f;
        if (!(x0   >= 0 && x0   < W_ && y0+1 >= 0 && y0+1 < H_)) wt2 = 0.f;
        if (!(x0+1 >= 0 && x0+1 < W_ && y0+1 >= 0 && y0+1 < H_)) wt3 = 0.f;

        __shared__ float red[D_];
        __shared__ float s_s[D_];
        __shared__ float s_part[D_];

        if (tid == 0) { while (ld_acq(&g_flagA) < NBLK_A) { } }
        __syncthreads();

        red[tid] = awsterm;
        __syncthreads();
        #pragma unroll
        for (int s = 128; s > 0; s >>= 1) {
            if (tid < s) red[tid] += red[tid + s];
            __syncthreads();
        }
        const float aws = red[0] + awsbias;

        float4 acc = make_float4(0.f, 0.f, 0.f, 0.f);
        #pragma unroll
        for (int ch = 0; ch < 16; ch++) {
            const float4 pp = *(const float4*)&g_part[b][ch][c][0];
            acc.x += pp.x; acc.y += pp.y; acc.z += pp.z; acc.w += pp.w;
        }
        const float v0 = fmaxf(acc.x + cb, 0.f);
        const float v1 = fmaxf(acc.y + cb, 0.f);
        const float v2 = fmaxf(acc.z + cb, 0.f);
        const float v3 = fmaxf(acc.w + cb, 0.f);
        s_s[c] = (wt0 * v0 + wt1 * v1 + wt2 * v2 + wt3 * v3) * aws;  // aw == 1
        __syncthreads();

        const float* sseg = s_s + qq * 64;
        const float* wr = (const float*)wreg;
        float part = 0.f;
        #pragma unroll
        for (int j = 0; j < 64; j++) part = fmaf(wr[j], sseg[j], part);
        s_part[tid] = part;
        __syncthreads();
        if (qq == 0)
            g_r[b][d] = ob + s_part[tid] + s_part[tid+1] + s_part[tid+2] + s_part[tid+3];
        __syncthreads();
        // Replay-determinism: last B block resets flagA (all B blocks passed the spin;
        // kernel-end implicit fence orders this before the next graph replay).
        if (tid == 0) {
            if (atomicAdd(&g_doneB, 1) == NBLK_B - 1) {
                g_flagA = 0;
                g_doneB = 0;
            }
        }
    }
}

// ============================================================================
// K2: out[b,q,:] = queries[b,q,:] + r[b,:]  — pure streaming kernel
// ============================================================================
__global__ __launch_bounds__(256) void k_stream(
    const float4* __restrict__ q4,
    float4* __restrict__ o4)
{
    const int blk = blockIdx.x;
    const int tid = threadIdx.x;
    const int base = blk * F4_PER_BLK + tid;

    __shared__ float4 sr[64];
    if (tid < 64)
        sr[tid] = ((const float4*)g_r)[(blk / 80) * 64 + tid];  // block's batch row

    float4 a[4];
    #pragma unroll
    for (int k = 0; k < 4; k++) a[k] = q4[base + k * 256];
    __syncthreads();

    const float4 rv = sr[tid & 63];   // (base + k*256) & 63 == tid & 63
    #pragma unroll
    for (int k = 0; k < 4; k++) {
        float4 t = a[k];
        t.x += rv.x; t.y += rv.y; t.z += rv.z; t.w += rv.w;
        o4[base + k * 256] = t;
    }
}

extern "C" void kernel_launch(void* const* d_in, const int* in_sizes, int n_in,
                              void* d_out, int out_size) {
    const float* queries     = (const float*)d_in[0];
    const float* navi        = (const float*)d_in[1];
    const float* bev         = (const float*)d_in[2];
    // d_in[3] spatial_shape unused (H=W=200 fixed)
    const float* point_score = (const float*)d_in[4];
    // d_in[5] aw_w, d_in[6] aw_b dead: softmax over size-1 axis == 1
    const float* aws_w       = (const float*)d_in[7];
    const float* aws_b       = (const float*)d_in[8];
    const float* conv_w      = (const float*)d_in[9];
    const float* conv_b      = (const float*)d_in[10];
    const float* out_w       = (const float*)d_in[11];
    const float* out_b       = (const float*)d_in[12];

    k_residual<<<NBLK_K1, 256>>>(navi, bev, point_score, aws_w, aws_b,
                                 conv_w, conv_b, out_w, out_b);
    k_stream<<<NBLK_K2, 256>>>((const float4*)queries, (float4*)d_out);
}

// round 6
// speedup vs baseline: 1.0152x; 1.0152x over previous
#include <cuda_runtime.h>
#include <math.h>

// Fixed shapes
#define B_   8
#define NQ_  1280
#define D_   256
#define CIN_ 64
#define H_   200
#define W_   200

// K1 roles: [0,128) conv stage A; [128,192) combine+GEMV stage B
#define NBLK_A 128        // (batch 8) x (ci-chunk 16), 4 input channels per chunk
#define NBLK_B 64         // (batch 8) x (row-group 8), 32 out_w rows per block
#define NBLK_K1 (NBLK_A + NBLK_B)

// K2: two half kernels; each 160 blocks x 256 thr x 8 float4 = 327680 f4
#define NBLK_K2 160
#define F4_HALF 327680

// Scratch + sync (no allocations allowed)
__device__ float g_part[B_][16][D_][4];  // conv partials per (batch, ci-chunk, co, corner)
__device__ float g_r[B_][D_];            // per-batch residual row
__device__ unsigned int g_flagA;
__device__ unsigned int g_doneB;

__device__ __forceinline__ unsigned int ld_acq(const unsigned int* p) {
    unsigned int v;
    asm volatile("ld.acquire.gpu.global.u32 %0, [%1];" : "=r"(v) : "l"(p) : "memory");
    return v;
}
__device__ __forceinline__ void red_rel_add(unsigned int* p, unsigned int v) {
    asm volatile("red.release.gpu.global.add.u32 [%0], %1;" :: "l"(p), "r"(v) : "memory");
}

// ============================================================================
// K1: per-batch residual row r[b][256]
// ============================================================================
__global__ __launch_bounds__(256) void k_residual(
    const float* __restrict__ navi,
    const float* __restrict__ bev,
    const float* __restrict__ point_score,
    const float* __restrict__ aws_w,
    const float* __restrict__ aws_b,
    const float* __restrict__ conv_w,
    const float* __restrict__ conv_b,
    const float* __restrict__ out_w,
    const float* __restrict__ out_b)
{
    // One 41KB buffer shared by both branches (static smem must stay < 48KB)
    __shared__ __align__(16) float sbuf[10280];
    __shared__ float red[D_];     // also reused as s_part in stage B
    __shared__ float s_s[D_];
    __shared__ float patch[4][16];

    const int blk = blockIdx.x;
    const int tid = threadIdx.x;

    if (blk < NBLK_A) {
        // ===== Stage A: 3x3 conv at the 4 bilinear corner pixels, 4 ci/block =====
        const int b     = blk >> 4;
        const int chunk = blk & 15;

        const float gx = (navi[2*b+1] * (1.0f/32.0f) + 1.0f) * (0.5f * W_) - 0.5f;
        const float gy = (navi[2*b+0] * (1.0f/32.0f) + 1.0f) * (0.5f * H_) - 0.5f;
        const int x0 = (int)floorf(gx);
        const int y0 = (int)floorf(gy);

        if (tid < 64) {
            const int ci_l = tid >> 4, pos = tid & 15;
            const int iy = y0 - 1 + (pos >> 2);
            const int ix = x0 - 1 + (pos & 3);
            float v = 0.0f;   // zero padding ('SAME')
            if (iy >= 0 && iy < H_ && ix >= 0 && ix < W_)
                v = bev[((b * CIN_ + chunk * 4 + ci_l) * H_ + iy) * W_ + ix];
            patch[ci_l][pos] = v;
        }

        // Coalesced weight staging: 2304 float4; linear f -> run r(=co), elem j
        // sbuf viewed as float4 with pitch 10 per co (36 floats + pad)
        {
            const float4* __restrict__ src = (const float4*)conv_w;
            float4* __restrict__ dst = (float4*)sbuf;
            #pragma unroll
            for (int i = 0; i < 9; i++) {
                const int f = i * 256 + tid;
                const int r = f / 9;
                const int j = f - r * 9;
                dst[r * 10 + j] = src[r * 144 + chunk * 9 + j];
            }
        }
        __syncthreads();

        float4 wq[9];
        {
            const float4* __restrict__ wsrc = (const float4*)sbuf + tid * 10;
            #pragma unroll
            for (int j = 0; j < 9; j++) wq[j] = wsrc[j];
        }
        const float* w = (const float*)wq;

        float a0 = 0.f, a1 = 0.f, a2 = 0.f, a3 = 0.f;
        #pragma unroll
        for (int cl = 0; cl < 4; cl++) {
            float p[16];
            #pragma unroll
            for (int j = 0; j < 16; j++) p[j] = patch[cl][j];
            const float* wc = w + cl * 9;
            #pragma unroll
            for (int kh = 0; kh < 3; kh++)
                #pragma unroll
                for (int kw = 0; kw < 3; kw++) {
                    const float wvv = wc[kh * 3 + kw];
                    a0 = fmaf(wvv, p[(kh + 0) * 4 + (kw + 0)], a0);
                    a1 = fmaf(wvv, p[(kh + 0) * 4 + (kw + 1)], a1);
                    a2 = fmaf(wvv, p[(kh + 1) * 4 + (kw + 0)], a2);
                    a3 = fmaf(wvv, p[(kh + 1) * 4 + (kw + 1)], a3);
                }
        }
        *(float4*)&g_part[b][chunk][tid][0] = make_float4(a0, a1, a2, a3);
        __syncthreads();
        if (tid == 0) red_rel_add(&g_flagA, 1);   // release: orders partials

    } else {
        // ===== Stage B: finish conv + bilinear + aws, then GEMV (32 rows/block) ===
        const int blkB  = blk - NBLK_A;
        const int b     = blkB >> 3;            // batch
        const int rg    = blkB & 7;             // row-group: rows [rg*32, rg*32+32)
        const int row_l = tid & 31;
        const int h     = tid >> 5;             // column chunk (8 x 32 cols)
        const int d     = rg * 32 + row_l;      // output row

        // --- Coalesced out_w staging: 2048 f4 (32 rows x 256 cols), 8 f4/thread.
        //     smem pitch 257 floats -> conflict-free GEMV reads.
        {
            const float4* __restrict__ src = (const float4*)out_w + (rg * 32) * 64;
            #pragma unroll
            for (int it = 0; it < 8; it++) {
                const int fidx = it * 256 + tid;      // 0..2047
                const int row  = fidx >> 6;           // 0..31
                const int c4   = fidx & 63;
                const float4 v = src[fidx];
                float* dst = sbuf + row * 257 + c4 * 4;
                dst[0] = v.x; dst[1] = v.y; dst[2] = v.z; dst[3] = v.w;
            }
        }

        // --- Pre-spin scalar work
        const int c = tid;
        const float v = (c < 128) ? point_score[2*b+1] : point_score[2*b+0];
        const int kk = (c & 127) >> 1;
        const float inv_t = exp2f(-(float)kk * (13.28771237954945f / 64.0f));
        const float arg = v * 6.283185307179586f * inv_t;
        const float e = (c & 1) ? cosf(arg) : sinf(arg);
        const float awsterm = e * aws_w[c];
        const float awsbias = aws_b[0];
        const float cb = conv_b[c];
        const float ob = out_b[rg * 32 + (tid & 31)];

        const float gx = (navi[2*b+1] * (1.0f/32.0f) + 1.0f) * (0.5f * W_) - 0.5f;
        const float gy = (navi[2*b+0] * (1.0f/32.0f) + 1.0f) * (0.5f * H_) - 0.5f;
        const float x0f = floorf(gx), y0f = floorf(gy);
        const float wx1 = gx - x0f, wy1 = gy - y0f;
        const int x0 = (int)x0f, y0 = (int)y0f;
        float wt0 = (1.f - wx1) * (1.f - wy1);
        float wt1 = wx1 * (1.f - wy1);
        float wt2 = (1.f - wx1) * wy1;
        float wt3 = wx1 * wy1;
        if (!(x0   >= 0 && x0   < W_ && y0   >= 0 && y0   < H_)) wt0 = 0.f;
        if (!(x0+1 >= 0 && x0+1 < W_ && y0   >= 0 && y0   < H_)) wt1 = 0.f;
        if (!(x0   >= 0 && x0   < W_ && y0+1 >= 0 && y0+1 < H_)) wt2 = 0.f;
        if (!(x0+1 >= 0 && x0+1 < W_ && y0+1 >= 0 && y0+1 < H_)) wt3 = 0.f;

        __syncthreads();   // staging visible

        if (tid == 0) { while (ld_acq(&g_flagA) < NBLK_A) { } }
        __syncthreads();

        // aws = sineembed(point_score) . aws_w + aws_b
        red[tid] = awsterm;
        __syncthreads();
        #pragma unroll
        for (int s = 128; s > 0; s >>= 1) {
            if (tid < s) red[tid] += red[tid + s];
            __syncthreads();
        }
        const float aws = red[0] + awsbias;

        // finish conv at 4 corners (+bias, ReLU), bilinear combine, scale by aws
        float4 acc = make_float4(0.f, 0.f, 0.f, 0.f);
        #pragma unroll
        for (int ch = 0; ch < 16; ch++) {
            const float4 pp = *(const float4*)&g_part[b][ch][c][0];
            acc.x += pp.x; acc.y += pp.y; acc.z += pp.z; acc.w += pp.w;
        }
        const float v0 = fmaxf(acc.x + cb, 0.f);
        const float v1 = fmaxf(acc.y + cb, 0.f);
        const float v2 = fmaxf(acc.z + cb, 0.f);
        const float v3 = fmaxf(acc.w + cb, 0.f);
        __syncthreads();   // red[] reuse barrier
        s_s[c] = (wt0 * v0 + wt1 * v1 + wt2 * v2 + wt3 * v3) * aws;  // aw == 1
        __syncthreads();

        // GEMV 1/8-row per thread, conflict-free smem reads (pitch 257)
        const float* wr = sbuf + row_l * 257 + h * 32;
        const float* ss = s_s + h * 32;
        float part = 0.f;
        #pragma unroll
        for (int i = 0; i < 32; i++) part = fmaf(wr[i], ss[i], part);
        red[tid] = part;   // red reused as s_part
        __syncthreads();
        if (tid < 32) {
            float r = ob;
            #pragma unroll
            for (int hh = 0; hh < 8; hh++) r += red[tid + hh * 32];
            g_r[b][d] = r;
        }
        __syncthreads();
        // Replay-determinism: last B block resets flagA (all B blocks passed the spin)
        if (tid == 0) {
            if (atomicAdd(&g_doneB, 1) == NBLK_B - 1) {
                g_flagA = 0;
                g_doneB = 0;
            }
        }
    }
}

// ============================================================================
// K2 (x2 halves): out[b,q,:] = queries[b,q,:] + r[b,:] — pure stream, no barrier
// ============================================================================
__global__ __launch_bounds__(256) void k_stream(
    const float4* __restrict__ q4,
    float4* __restrict__ o4,
    int half)
{
    const int blk = blockIdx.x;
    const int tid = threadIdx.x;
    const int base = half * F4_HALF + blk * 2048 + tid;
    const int batch = (half * NBLK_K2 + blk) / 40;   // 40 blocks per batch

    // residual float4 for this thread: (base + k*256) & 63 == tid & 63
    const float4 rv = ((const float4*)g_r)[batch * 64 + (tid & 63)];

    float4 a[8];
    #pragma unroll
    for (int k = 0; k < 8; k++) a[k] = q4[base + k * 256];
    #pragma unroll
    for (int k = 0; k < 8; k++) {
        float4 t = a[k];
        t.x += rv.x; t.y += rv.y; t.z += rv.z; t.w += rv.w;
        o4[base + k * 256] = t;
    }
}

extern "C" void kernel_launch(void* const* d_in, const int* in_sizes, int n_in,
                              void* d_out, int out_size) {
    const float* queries     = (const float*)d_in[0];
    const float* navi        = (const float*)d_in[1];
    const float* bev         = (const float*)d_in[2];
    // d_in[3] spatial_shape unused (H=W=200 fixed)
    const float* point_score = (const float*)d_in[4];
    // d_in[5] aw_w, d_in[6] aw_b dead: softmax over size-1 axis == 1
    const float* aws_w       = (const float*)d_in[7];
    const float* aws_b       = (const float*)d_in[8];
    const float* conv_w      = (const float*)d_in[9];
    const float* conv_b      = (const float*)d_in[10];
    const float* out_w       = (const float*)d_in[11];
    const float* out_b       = (const float*)d_in[12];

    k_residual<<<NBLK_K1, 256>>>(navi, bev, point_score, aws_w, aws_b,
                                 conv_w, conv_b, out_w, out_b);
    k_stream<<<NBLK_K2, 256>>>((const float4*)queries, (float4*)d_out, 0);
    k_stream<<<NBLK_K2, 256>>>((const float4*)queries, (float4*)d_out, 1);
}

// round 9
// speedup vs baseline: 1.3145x; 1.2948x over previous
#include <cuda_runtime.h>
#include <math.h>

// Fixed shapes
#define B_   8
#define NQ_  1280
#define D_   256
#define CIN_ 64
#define H_   200
#define W_   200

// K1 roles: [0,128) conv stage A; [128,192) combine+GEMV stage B
#define NBLK_A 128        // (batch 8) x (ci-chunk 16), 4 input channels per chunk
#define NBLK_B 64         // (batch 8) x (row-group 8), 32 out_w rows per block
#define NBLK_K1 (NBLK_A + NBLK_B)

// K2: 640 blocks x 256 thr x 4 float4 = 655360 f4 = 8*1280*256 floats
#define NBLK_K2 640
#define F4_PER_BLK 1024

// Scratch + sync (no allocations allowed)
__device__ float g_part[B_][16][D_][4];  // conv partials (batch, ci-chunk, co, corner)
__device__ float g_r[B_][D_];            // per-batch residual row
__device__ unsigned int g_flagA[B_];     // per-batch A-completion counters (-> 16)
__device__ unsigned int g_doneB[B_];     // per-batch B-completion counters (-> 8)

__device__ __forceinline__ unsigned int ld_acq(const unsigned int* p) {
    unsigned int v;
    asm volatile("ld.acquire.gpu.global.u32 %0, [%1];" : "=r"(v) : "l"(p) : "memory");
    return v;
}
__device__ __forceinline__ void red_rel_add(unsigned int* p, unsigned int v) {
    asm volatile("red.release.gpu.global.add.u32 [%0], %1;" :: "l"(p), "r"(v) : "memory");
}

// ============================================================================
// K1: per-batch residual row r[b][256]
// ============================================================================
__global__ __launch_bounds__(256) void k_residual(
    const float* __restrict__ navi,
    const float* __restrict__ bev,
    const float* __restrict__ point_score,
    const float* __restrict__ aws_w,
    const float* __restrict__ aws_b,
    const float* __restrict__ conv_w,
    const float* __restrict__ conv_b,
    const float* __restrict__ out_w,
    const float* __restrict__ out_b)
{
    // One 41KB buffer shared by both branches (static smem < 48KB)
    __shared__ __align__(16) float sbuf[10280];
    __shared__ float red[D_];
    __shared__ float s_s[D_];
    __shared__ float patch[4][16];

    const int blk = blockIdx.x;
    const int tid = threadIdx.x;

    if (blk < NBLK_A) {
        // ===== Stage A: conv at the 4 bilinear corner pixels, 4 ci/block =========
        const int b     = blk >> 4;
        const int chunk = blk & 15;

        // 1) Issue navi loads FIRST (critical-path head)
        const float n0 = navi[2*b+0];
        const float n1 = navi[2*b+1];

        // 2) Issue all 9 weight LDGs next (overlaps the navi->patch chain)
        const float4* __restrict__ src = (const float4*)conv_w;
        float4 wld[9];
        #pragma unroll
        for (int i = 0; i < 9; i++) {
            const int f = i * 256 + tid;
            const int r = f / 9;
            const int j = f - r * 9;
            wld[i] = src[r * 144 + chunk * 9 + j];
        }

        // 3) Coords + patch load (depends on navi; weights already in flight)
        const float gx = (n1 * (1.0f/32.0f) + 1.0f) * (0.5f * W_) - 0.5f;
        const float gy = (n0 * (1.0f/32.0f) + 1.0f) * (0.5f * H_) - 0.5f;
        const int x0 = (int)floorf(gx);
        const int y0 = (int)floorf(gy);
        if (tid < 64) {
            const int ci_l = tid >> 4, pos = tid & 15;
            const int iy = y0 - 1 + (pos >> 2);
            const int ix = x0 - 1 + (pos & 3);
            float v = 0.0f;   // zero padding ('SAME')
            if (iy >= 0 && iy < H_ && ix >= 0 && ix < W_)
                v = bev[((b * CIN_ + chunk * 4 + ci_l) * H_ + iy) * W_ + ix];
            patch[ci_l][pos] = v;
        }

        // 4) Drain weight loads into smem (pitch 10 f4 per co)
        {
            float4* __restrict__ dst = (float4*)sbuf;
            #pragma unroll
            for (int i = 0; i < 9; i++) {
                const int f = i * 256 + tid;
                const int r = f / 9;
                const int j = f - r * 9;
                dst[r * 10 + j] = wld[i];
            }
        }
        __syncthreads();

        float4 wq[9];
        {
            const float4* __restrict__ wsrc = (const float4*)sbuf + tid * 10;
            #pragma unroll
            for (int j = 0; j < 9; j++) wq[j] = wsrc[j];
        }
        const float* w = (const float*)wq;

        float a0 = 0.f, a1 = 0.f, a2 = 0.f, a3 = 0.f;
        #pragma unroll
        for (int cl = 0; cl < 4; cl++) {
            float p[16];
            #pragma unroll
            for (int j = 0; j < 16; j++) p[j] = patch[cl][j];
            const float* wc = w + cl * 9;
            #pragma unroll
            for (int kh = 0; kh < 3; kh++)
                #pragma unroll
                for (int kw = 0; kw < 3; kw++) {
                    const float wvv = wc[kh * 3 + kw];
                    a0 = fmaf(wvv, p[(kh + 0) * 4 + (kw + 0)], a0);
                    a1 = fmaf(wvv, p[(kh + 0) * 4 + (kw + 1)], a1);
                    a2 = fmaf(wvv, p[(kh + 1) * 4 + (kw + 0)], a2);
                    a3 = fmaf(wvv, p[(kh + 1) * 4 + (kw + 1)], a3);
                }
        }
        *(float4*)&g_part[b][chunk][tid][0] = make_float4(a0, a1, a2, a3);
        __syncthreads();
        if (tid == 0) red_rel_add(&g_flagA[b], 1);   // release (per-batch)

    } else {
        // ===== Stage B: finish conv + bilinear + aws, then GEMV (32 rows/block) ===
        const int blkB  = blk - NBLK_A;
        const int b     = blkB >> 3;            // batch
        const int rg    = blkB & 7;             // rows [rg*32, rg*32+32)
        const int row_l = tid & 31;
        const int h     = tid >> 5;             // column chunk (8 x 32 cols)
        const int d     = rg * 32 + row_l;

        // Coalesced out_w staging (issues immediately; pitch 257 -> conflict-free)
        {
            const float4* __restrict__ src = (const float4*)out_w + (rg * 32) * 64;
            #pragma unroll
            for (int it = 0; it < 8; it++) {
                const int fidx = it * 256 + tid;
                const int row  = fidx >> 6;
                const int c4   = fidx & 63;
                const float4 v = src[fidx];
                float* dst = sbuf + row * 257 + c4 * 4;
                dst[0] = v.x; dst[1] = v.y; dst[2] = v.z; dst[3] = v.w;
            }
        }

        // Pre-spin scalar work
        const int c = tid;
        const float v = (c < 128) ? point_score[2*b+1] : point_score[2*b+0];
        const int kk = (c & 127) >> 1;
        const float inv_t = exp2f(-(float)kk * (13.28771237954945f / 64.0f));
        const float arg = v * 6.283185307179586f * inv_t;
        const float e = (c & 1) ? cosf(arg) : sinf(arg);
        const float awsterm = e * aws_w[c];
        const float awsbias = aws_b[0];
        const float cb = conv_b[c];
        const float ob = out_b[d];

        const float gx = (navi[2*b+1] * (1.0f/32.0f) + 1.0f) * (0.5f * W_) - 0.5f;
        const float gy = (navi[2*b+0] * (1.0f/32.0f) + 1.0f) * (0.5f * H_) - 0.5f;
        const float x0f = floorf(gx), y0f = floorf(gy);
        const float wx1 = gx - x0f, wy1 = gy - y0f;
        const int x0 = (int)x0f, y0 = (int)y0f;
        float wt0 = (1.f - wx1) * (1.f - wy1);
        float wt1 = wx1 * (1.f - wy1);
        float wt2 = (1.f - wx1) * wy1;
        float wt3 = wx1 * wy1;
        if (!(x0   >= 0 && x0   < W_ && y0   >= 0 && y0   < H_)) wt0 = 0.f;
        if (!(x0+1 >= 0 && x0+1 < W_ && y0   >= 0 && y0   < H_)) wt1 = 0.f;
        if (!(x0   >= 0 && x0   < W_ && y0+1 >= 0 && y0+1 < H_)) wt2 = 0.f;
        if (!(x0+1 >= 0 && x0+1 < W_ && y0+1 >= 0 && y0+1 < H_)) wt3 = 0.f;

        // aws reduction: shuffle within warps, tiny cross-warp pass (1 barrier)
        float t = awsterm;
        #pragma unroll
        for (int o = 16; o > 0; o >>= 1) t += __shfl_xor_sync(0xFFFFFFFFu, t, o);
        if ((tid & 31) == 0) red[tid >> 5] = t;
        __syncthreads();                      // also makes out_w staging visible
        if (tid == 0) {
            float s = red[0];
            #pragma unroll
            for (int j = 1; j < 8; j++) s += red[j];
            red[0] = s + awsbias;
        }

        // Wait for THIS batch's 16 A blocks
        if (tid == 32) { while (ld_acq(&g_flagA[b]) < 16) { } }
        __syncthreads();
        const float aws = red[0];

        // finish conv at 4 corners (+bias, ReLU), bilinear combine, scale by aws
        float4 acc = make_float4(0.f, 0.f, 0.f, 0.f);
        #pragma unroll
        for (int ch = 0; ch < 16; ch++) {
            const float4 pp = *(const float4*)&g_part[b][ch][c][0];
            acc.x += pp.x; acc.y += pp.y; acc.z += pp.z; acc.w += pp.w;
        }
        const float v0 = fmaxf(acc.x + cb, 0.f);
        const float v1 = fmaxf(acc.y + cb, 0.f);
        const float v2 = fmaxf(acc.z + cb, 0.f);
        const float v3 = fmaxf(acc.w + cb, 0.f);
        s_s[c] = (wt0 * v0 + wt1 * v1 + wt2 * v2 + wt3 * v3) * aws;  // aw == 1
        __syncthreads();

        // GEMV 1/8-row per thread, conflict-free smem (pitch 257)
        const float* wr = sbuf + row_l * 257 + h * 32;
        const float* ss = s_s + h * 32;
        float part = 0.f;
        #pragma unroll
        for (int i = 0; i < 32; i++) part = fmaf(wr[i], ss[i], part);
        red[tid] = part;
        __syncthreads();
        if (tid < 32) {
            float r = ob;
            #pragma unroll
            for (int hh = 0; hh < 8; hh++) r += red[tid + hh * 32];
            g_r[b][rg * 32 + tid] = r;
        }
        __syncthreads();
        // Replay determinism: last B block of batch resets its batch flags
        if (tid == 0) {
            if (atomicAdd(&g_doneB[b], 1) == 7) {
                g_flagA[b] = 0;
                g_doneB[b] = 0;
            }
        }
    }
}

// ============================================================================
// K2: out[b,q,:] = queries[b,q,:] + r[b,:]  — pure stream
// ============================================================================
__global__ __launch_bounds__(256) void k_stream(
    const float4* __restrict__ q4,
    float4* __restrict__ o4)
{
    const int blk = blockIdx.x;
    const int tid = threadIdx.x;
    const int base = blk * F4_PER_BLK + tid;
    const int batch = blk / 80;   // 80 blocks per batch

    // residual float4 for this thread: (base + k*256) & 63 == tid & 63
    const float4 rv = ((const float4*)g_r)[batch * 64 + (tid & 63)];

    float4 a[4];
    #pragma unroll
    for (int k = 0; k < 4; k++) a[k] = q4[base + k * 256];
    #pragma unroll
    for (int k = 0; k < 4; k++) {
        float4 t = a[k];
        t.x += rv.x; t.y += rv.y; t.z += rv.z; t.w += rv.w;
        o4[base + k * 256] = t;
    }
}

extern "C" void kernel_launch(void* const* d_in, const int* in_sizes, int n_in,
                              void* d_out, int out_size) {
    const float* queries     = (const float*)d_in[0];
    const float* navi        = (const float*)d_in[1];
    const float* bev         = (const float*)d_in[2];
    // d_in[3] spatial_shape unused (H=W=200 fixed)
    const float* point_score = (const float*)d_in[4];
    // d_in[5] aw_w, d_in[6] aw_b dead: softmax over size-1 axis == 1
    const float* aws_w       = (const float*)d_in[7];
    const float* aws_b       = (const float*)d_in[8];
    const float* conv_w      = (const float*)d_in[9];
    const float* conv_b      = (const float*)d_in[10];
    const float* out_w       = (const float*)d_in[11];
    const float* out_b       = (const float*)d_in[12];

    k_residual<<<NBLK_K1, 256>>>(navi, bev, point_score, aws_w, aws_b,
                                 conv_w, conv_b, out_w, out_b);
    k_stream<<<NBLK_K2, 256>>>((const float4*)queries, (float4*)d_out);
}